// round 1
// baseline (speedup 1.0000x reference)
#include <cuda_runtime.h>
#include <stdint.h>

#define NN 50000
#define NE 640000
#define NG 256
#define HH 128
#define LL 4

// ---------------- scratch (device globals: allocation-free) ----------------
__device__ float g_h[NN * HH];                 // 25.6 MB
__device__ float g_e[(size_t)NE * HH];         // 327.7 MB
__device__ float g_agg[NN * HH];               // 25.6 MB

// ---------------- packed fp32x2 FMA (FFMA2) ----------------
__device__ __forceinline__ float2 ffma2(float2 a, float2 b, float2 c) {
    unsigned long long ua = *reinterpret_cast<unsigned long long*>(&a);
    unsigned long long ub = *reinterpret_cast<unsigned long long*>(&b);
    unsigned long long uc = *reinterpret_cast<unsigned long long*>(&c);
    unsigned long long ud;
    asm("fma.rn.f32x2 %0, %1, %2, %3;" : "=l"(ud) : "l"(ua), "l"(ub), "l"(uc));
    return *reinterpret_cast<float2*>(&ud);
}

// ---------------- small utility kernels ----------------
__global__ void zero_out_kernel(float* out) {
    int i = blockIdx.x * blockDim.x + threadIdx.x;   // grid sized exactly NG*HH
    out[i] = 0.0f;
}

__global__ void zero_agg_kernel() {
    int i = blockIdx.x * blockDim.x + threadIdx.x;   // grid sized exactly NN*HH/4
    float4 z = make_float4(0.f, 0.f, 0.f, 0.f);
    reinterpret_cast<float4*>(g_agg)[i] = z;
}

// ---------------- embeddings ----------------
// h = [x|p] @ W_embed + b_embed   (N x 80 @ 80 x 128)
__global__ void embed_nodes_kernel(const float* __restrict__ x, const float* __restrict__ p,
                                   const float* __restrict__ W, const float* __restrict__ b) {
    __shared__ float Ws[80 * HH];     // 40 KB
    __shared__ float As[16][81];
    int tid = threadIdx.x;            // blockDim = 128
    for (int i = tid; i < 80 * HH; i += 128) Ws[i] = W[i];
    float bias = b[tid];
    __syncthreads();
    for (int chunk = blockIdx.x; chunk < NN / 16; chunk += gridDim.x) {
        int n0 = chunk * 16;
        __syncthreads();
        for (int i = tid; i < 16 * 64; i += 128) { int r = i >> 6, c = i & 63; As[r][c]      = x[(n0 + r) * 64 + c]; }
        for (int i = tid; i < 16 * 16; i += 128) { int r = i >> 4, c = i & 15; As[r][64 + c] = p[(n0 + r) * 16 + c]; }
        __syncthreads();
        #pragma unroll 4
        for (int r = 0; r < 16; r++) {
            float acc = bias;
            #pragma unroll
            for (int k = 0; k < 80; k++) acc += As[r][k] * Ws[k * HH + tid];
            g_h[(n0 + r) * HH + tid] = acc;
        }
    }
}

// e = e_attr @ W_eembed + b_eembed  (E x 16 @ 16 x 128)
__global__ void embed_edges_kernel(const float* __restrict__ ea,
                                   const float* __restrict__ W, const float* __restrict__ b) {
    __shared__ float Ws[16 * HH];     // 8 KB
    __shared__ float As[32][17];
    int tid = threadIdx.x;            // blockDim = 128
    for (int i = tid; i < 16 * HH; i += 128) Ws[i] = W[i];
    float bias = b[tid];
    __syncthreads();
    for (int chunk = blockIdx.x; chunk < NE / 32; chunk += gridDim.x) {
        int e0 = chunk * 32;
        __syncthreads();
        for (int i = tid; i < 32 * 16; i += 128) { int r = i >> 4, c = i & 15; As[r][c] = ea[(e0 + r) * 16 + c]; }
        __syncthreads();
        #pragma unroll 4
        for (int r = 0; r < 32; r++) {
            float acc = bias;
            #pragma unroll
            for (int k = 0; k < 16; k++) acc += As[r][k] * Ws[k * HH + tid];
            g_e[(size_t)(e0 + r) * HH + tid] = acc;
        }
    }
}

// ---------------- edge kernel: cat=[h_send|h_rec|e] @ [Wm|We], scatter msg, write e ----------------
// Tile: 128 edges x 256 outcols, K=384, chunks of 16.
// blockDim 512 (16 warps); warp w owns edges w*8..w*8+7, all 256 cols (8 per lane, as 4 f32x2).
#define TE 128
#define KC 16
__global__ __launch_bounds__(512, 1)
void edge_kernel(const int* __restrict__ send, const int* __restrict__ rec,
                 const float* __restrict__ Wm_l, const float* __restrict__ We_l,
                 const float* __restrict__ bm_l, const float* __restrict__ be_l) {
    __shared__ float2 As[KC][TE + 1];   // (a,a) duplicated; 16.5 KB; pad -> conflict-free STS
    __shared__ float2 Bs[KC][HH];       // (Wm[k][c], We[k][c]); 16 KB
    __shared__ int rowS[TE], rowR[TE];

    const int tid  = threadIdx.x;
    const int warp = tid >> 5;
    const int lane = tid & 31;
    const int e0   = blockIdx.x * TE;   // NE = 5000 * 128 exact

    if (tid < TE) {
        rowS[tid] = send[e0 + tid] * HH;
        rowR[tid] = rec [e0 + tid] * HH;
    }

    float2 acc[8][4];
    #pragma unroll
    for (int i = 0; i < 8; i++)
        #pragma unroll
        for (int j = 0; j < 4; j++) acc[i][j] = make_float2(0.f, 0.f);

    __syncthreads();

    for (int k0 = 0; k0 < 3 * HH; k0 += KC) {
        const int region = k0 >> 7;   // 0: h_send, 1: h_rec, 2: e (chunks never straddle)
        // A tile: 2048 values, 4/thread; lanes sweep k (64B contiguous per edge-row segment)
        #pragma unroll
        for (int i = 0; i < 4; i++) {
            int idx = tid + i * 512;
            int kk = idx & (KC - 1);
            int e  = idx >> 4;
            float v;
            if (region == 0)      v = g_h[rowS[e] + k0 + kk];
            else if (region == 1) v = g_h[rowR[e] + (k0 - HH) + kk];
            else                  v = g_e[(size_t)(e0 + e) * HH + (k0 - 2 * HH) + kk];
            As[kk][e] = make_float2(v, v);
        }
        // B tile: 2048 float2, 4/thread; coalesced rows of Wm/We
        #pragma unroll
        for (int i = 0; i < 4; i++) {
            int idx = tid + i * 512;
            int c  = idx & (HH - 1);
            int kk = idx >> 7;
            int kr = (k0 + kk) * HH + c;
            Bs[kk][c] = make_float2(Wm_l[kr], We_l[kr]);
        }
        __syncthreads();
        #pragma unroll
        for (int kk = 0; kk < KC; kk++) {
            float2 b0 = Bs[kk][lane];
            float2 b1 = Bs[kk][lane + 32];
            float2 b2 = Bs[kk][lane + 64];
            float2 b3 = Bs[kk][lane + 96];
            #pragma unroll
            for (int i = 0; i < 8; i++) {
                float2 a = As[kk][warp * 8 + i];   // broadcast LDS.64
                acc[i][0] = ffma2(a, b0, acc[i][0]);
                acc[i][1] = ffma2(a, b1, acc[i][1]);
                acc[i][2] = ffma2(a, b2, acc[i][2]);
                acc[i][3] = ffma2(a, b3, acc[i][3]);
            }
        }
        __syncthreads();
    }

    float bmv[4], bev[4];
    #pragma unroll
    for (int j = 0; j < 4; j++) { bmv[j] = bm_l[lane + 32 * j]; bev[j] = be_l[lane + 32 * j]; }

    #pragma unroll
    for (int i = 0; i < 8; i++) {
        int le = warp * 8 + i;
        float* aggRow = g_agg + rowR[le];
        float* eRow   = g_e + (size_t)(e0 + le) * HH;   // in-place safe: row fully consumed
        #pragma unroll
        for (int j = 0; j < 4; j++) {
            int c = lane + 32 * j;
            atomicAdd(aggRow + c, acc[i][j].x + bmv[j]);  // message + bm scattered to rec
            eRow[c] = acc[i][j].y + bev[j];               // e update + be
        }
    }
}

// ---------------- node kernel: h = [h|agg] @ Wh + bh ----------------
// Tile: 64 nodes x 128 cols, K=256, chunks of 32. blockDim 256 (8 warps, 8 nodes/warp).
#define TN 64
#define NKC 32
__global__ __launch_bounds__(256, 2)
void node_kernel(const float* __restrict__ Wh_l, const float* __restrict__ bh_l) {
    __shared__ float2 As[NKC][TN + 1];  // (a,a); 16.6 KB
    __shared__ float2 Bs[NKC][64];      // (Wh[k][c], Wh[k][c+64]); 16 KB

    const int tid  = threadIdx.x;
    const int warp = tid >> 5;
    const int lane = tid & 31;
    const int n0   = blockIdx.x * TN;

    float2 acc[8][2];
    #pragma unroll
    for (int i = 0; i < 8; i++) { acc[i][0] = make_float2(0.f, 0.f); acc[i][1] = make_float2(0.f, 0.f); }

    for (int k0 = 0; k0 < 2 * HH; k0 += NKC) {
        const int region = k0 >> 7;   // 0: h, 1: agg
        #pragma unroll
        for (int i = 0; i < 8; i++) {
            int idx = tid + i * 256;
            int kk = idx & (NKC - 1);
            int r  = idx >> 5;
            int n  = n0 + r;
            float v = 0.f;
            if (n < NN) {
                if (region == 0) v = g_h  [n * HH + k0 + kk];
                else             v = g_agg[n * HH + (k0 - HH) + kk];
            }
            As[kk][r] = make_float2(v, v);
        }
        #pragma unroll
        for (int i = 0; i < 8; i++) {
            int idx = tid + i * 256;
            int c  = idx & 63;
            int kk = idx >> 6;
            int kr = (k0 + kk) * HH + c;
            Bs[kk][c] = make_float2(Wh_l[kr], Wh_l[kr + 64]);
        }
        __syncthreads();
        #pragma unroll
        for (int kk = 0; kk < NKC; kk++) {
            float2 b0 = Bs[kk][lane];
            float2 b1 = Bs[kk][lane + 32];
            #pragma unroll
            for (int i = 0; i < 8; i++) {
                float2 a = As[kk][warp * 8 + i];
                acc[i][0] = ffma2(a, b0, acc[i][0]);
                acc[i][1] = ffma2(a, b1, acc[i][1]);
            }
        }
        __syncthreads();
    }

    float bh0 = bh_l[lane], bh1 = bh_l[lane + 32], bh2 = bh_l[lane + 64], bh3 = bh_l[lane + 96];
    #pragma unroll
    for (int i = 0; i < 8; i++) {
        int n = n0 + warp * 8 + i;
        if (n < NN) {
            float* hRow = g_h + n * HH;                  // in-place safe
            hRow[lane]      = acc[i][0].x + bh0;
            hRow[lane + 32] = acc[i][1].x + bh1;
            hRow[lane + 64] = acc[i][0].y + bh2;
            hRow[lane + 96] = acc[i][1].y + bh3;
        }
    }
}

// ---------------- global add pool ----------------
__global__ void pool_kernel(const int* __restrict__ batch, float* __restrict__ out) {
    int gidx = blockIdx.x * blockDim.x + threadIdx.x;
    int n = gidx >> 5, lane = gidx & 31;
    if (n >= NN) return;
    int g = batch[n];
    float4 v = reinterpret_cast<const float4*>(g_h + (size_t)n * HH)[lane];
    float* o = out + g * HH + lane * 4;
    atomicAdd(o + 0, v.x); atomicAdd(o + 1, v.y);
    atomicAdd(o + 2, v.z); atomicAdd(o + 3, v.w);
}

// ---------------- launch ----------------
extern "C" void kernel_launch(void* const* d_in, const int* in_sizes, int n_in,
                              void* d_out, int out_size) {
    // Identify inputs by element count (ordered disambiguation for duplicates).
    const float *x = 0, *p = 0, *e_attr = 0, *W_embed = 0, *b_embed = 0, *W_eembed = 0, *b_eembed = 0;
    const float *Wm = 0, *bm = 0, *Wh = 0, *bh = 0, *We = 0, *be = 0;
    const int *edge_index = 0, *batch = 0;
    int n128 = 0, n512 = 0, n196k = 0;
    for (int i = 0; i < n_in; i++) {
        long s = in_sizes[i];
        const void* ptr = d_in[i];
        switch (s) {
            case 3200000:  x         = (const float*)ptr; break;   // [50000,64]
            case 800000:   p         = (const float*)ptr; break;   // [50000,16]
            case 10240000: e_attr    = (const float*)ptr; break;   // [640000,16]
            case 1280000:  edge_index= (const int*)ptr;   break;   // [2,640000]
            case 50000:    batch     = (const int*)ptr;   break;   // [50000]
            case 10240:    W_embed   = (const float*)ptr; break;   // [80,128]
            case 2048:     W_eembed  = (const float*)ptr; break;   // [16,128]
            case 131072:   Wh        = (const float*)ptr; break;   // [4,256,128]
            case 128:  if (n128++ == 0) b_embed = (const float*)ptr; else b_eembed = (const float*)ptr; break;
            case 196608: if (n196k++ == 0) Wm  = (const float*)ptr; else We       = (const float*)ptr; break;
            case 512:
                if (n512 == 0) bm = (const float*)ptr;
                else if (n512 == 1) bh = (const float*)ptr;
                else be = (const float*)ptr;
                n512++;
                break;
            default: break;
        }
    }

    const int* send = edge_index;
    const int* rec  = edge_index + NE;
    float* out = (float*)d_out;

    zero_out_kernel<<<(NG * HH) / 256, 256>>>(out);
    embed_nodes_kernel<<<1024, 128>>>(x, p, W_embed, b_embed);
    embed_edges_kernel<<<2048, 128>>>(e_attr, W_eembed, b_eembed);

    for (int l = 0; l < LL; l++) {
        zero_agg_kernel<<<(NN * HH / 4) / 256, 256>>>();
        edge_kernel<<<NE / TE, 512>>>(send, rec,
                                      Wm + (size_t)l * 3 * HH * HH,
                                      We + (size_t)l * 3 * HH * HH,
                                      bm + l * HH, be + l * HH);
        node_kernel<<<(NN + TN - 1) / TN, 256>>>(Wh + (size_t)l * 2 * HH * HH, bh + l * HH);
    }

    pool_kernel<<<(NN * 32 + 255) / 256, 256>>>(batch, out);
}

// round 2
// speedup vs baseline: 1.0005x; 1.0005x over previous
#include <cuda_runtime.h>
#include <stdint.h>

#define NN 50000
#define NE 640000
#define NG 256
#define HH 128
#define LL 4

// ---------------- scratch (device globals: allocation-free) ----------------
__device__ float g_h[NN * HH];                 // 25.6 MB
__device__ float g_e[(size_t)NE * HH];         // 327.7 MB
__device__ float g_agg[NN * HH];               // 25.6 MB

// ---------------- packed fp32x2 FMA (FFMA2) ----------------
__device__ __forceinline__ float2 ffma2(float2 a, float2 b, float2 c) {
    unsigned long long ua = *reinterpret_cast<unsigned long long*>(&a);
    unsigned long long ub = *reinterpret_cast<unsigned long long*>(&b);
    unsigned long long uc = *reinterpret_cast<unsigned long long*>(&c);
    unsigned long long ud;
    asm("fma.rn.f32x2 %0, %1, %2, %3;" : "=l"(ud) : "l"(ua), "l"(ub), "l"(uc));
    return *reinterpret_cast<float2*>(&ud);
}

// ---------------- small utility kernels ----------------
__global__ void zero_out_kernel(float* out) {
    int i = blockIdx.x * blockDim.x + threadIdx.x;   // grid sized exactly NG*HH
    out[i] = 0.0f;
}

__global__ void zero_agg_kernel() {
    int i = blockIdx.x * blockDim.x + threadIdx.x;   // grid sized exactly NN*HH/4
    float4 z = make_float4(0.f, 0.f, 0.f, 0.f);
    reinterpret_cast<float4*>(g_agg)[i] = z;
}

// ---------------- embeddings ----------------
// h = [x|p] @ W_embed + b_embed   (N x 80 @ 80 x 128)
__global__ void embed_nodes_kernel(const float* __restrict__ x, const float* __restrict__ p,
                                   const float* __restrict__ W, const float* __restrict__ b) {
    __shared__ float Ws[80 * HH];     // 40 KB
    __shared__ float As[16][81];
    int tid = threadIdx.x;            // blockDim = 128
    for (int i = tid; i < 80 * HH; i += 128) Ws[i] = W[i];
    float bias = b[tid];
    __syncthreads();
    for (int chunk = blockIdx.x; chunk < NN / 16; chunk += gridDim.x) {
        int n0 = chunk * 16;
        __syncthreads();
        for (int i = tid; i < 16 * 64; i += 128) { int r = i >> 6, c = i & 63; As[r][c]      = x[(n0 + r) * 64 + c]; }
        for (int i = tid; i < 16 * 16; i += 128) { int r = i >> 4, c = i & 15; As[r][64 + c] = p[(n0 + r) * 16 + c]; }
        __syncthreads();
        #pragma unroll 4
        for (int r = 0; r < 16; r++) {
            float acc = bias;
            #pragma unroll
            for (int k = 0; k < 80; k++) acc += As[r][k] * Ws[k * HH + tid];
            g_h[(n0 + r) * HH + tid] = acc;
        }
    }
}

// e = e_attr @ W_eembed + b_eembed  (E x 16 @ 16 x 128)
__global__ void embed_edges_kernel(const float* __restrict__ ea,
                                   const float* __restrict__ W, const float* __restrict__ b) {
    __shared__ float Ws[16 * HH];     // 8 KB
    __shared__ float As[32][17];
    int tid = threadIdx.x;            // blockDim = 128
    for (int i = tid; i < 16 * HH; i += 128) Ws[i] = W[i];
    float bias = b[tid];
    __syncthreads();
    for (int chunk = blockIdx.x; chunk < NE / 32; chunk += gridDim.x) {
        int e0 = chunk * 32;
        __syncthreads();
        for (int i = tid; i < 32 * 16; i += 128) { int r = i >> 4, c = i & 15; As[r][c] = ea[(e0 + r) * 16 + c]; }
        __syncthreads();
        #pragma unroll 4
        for (int r = 0; r < 32; r++) {
            float acc = bias;
            #pragma unroll
            for (int k = 0; k < 16; k++) acc += As[r][k] * Ws[k * HH + tid];
            g_e[(size_t)(e0 + r) * HH + tid] = acc;
        }
    }
}

// ---------------- edge kernel: cat=[h_send|h_rec|e] @ [Wm|We], scatter msg, write e ----------------
// Tile: 128 edges x 256 outcols, K=384, chunks of 16.
// blockDim 512 (16 warps); warp w owns edges w*8..w*8+7, all 256 cols (8 per lane, as 4 f32x2).
#define TE 128
#define KC 16
__global__ __launch_bounds__(512, 1)
void edge_kernel(const int* __restrict__ send, const int* __restrict__ rec,
                 const float* __restrict__ Wm_l, const float* __restrict__ We_l,
                 const float* __restrict__ bm_l, const float* __restrict__ be_l) {
    __shared__ float2 As[KC][TE + 1];   // (a,a) duplicated; 16.5 KB; pad -> conflict-free STS
    __shared__ float2 Bs[KC][HH];       // (Wm[k][c], We[k][c]); 16 KB
    __shared__ int rowS[TE], rowR[TE];

    const int tid  = threadIdx.x;
    const int warp = tid >> 5;
    const int lane = tid & 31;
    const int e0   = blockIdx.x * TE;   // NE = 5000 * 128 exact

    if (tid < TE) {
        rowS[tid] = send[e0 + tid] * HH;
        rowR[tid] = rec [e0 + tid] * HH;
    }

    float2 acc[8][4];
    #pragma unroll
    for (int i = 0; i < 8; i++)
        #pragma unroll
        for (int j = 0; j < 4; j++) acc[i][j] = make_float2(0.f, 0.f);

    __syncthreads();

    for (int k0 = 0; k0 < 3 * HH; k0 += KC) {
        const int region = k0 >> 7;   // 0: h_send, 1: h_rec, 2: e (chunks never straddle)
        // A tile: 2048 values, 4/thread; lanes sweep k (64B contiguous per edge-row segment)
        #pragma unroll
        for (int i = 0; i < 4; i++) {
            int idx = tid + i * 512;
            int kk = idx & (KC - 1);
            int e  = idx >> 4;
            float v;
            if (region == 0)      v = g_h[rowS[e] + k0 + kk];
            else if (region == 1) v = g_h[rowR[e] + (k0 - HH) + kk];
            else                  v = g_e[(size_t)(e0 + e) * HH + (k0 - 2 * HH) + kk];
            As[kk][e] = make_float2(v, v);
        }
        // B tile: 2048 float2, 4/thread; coalesced rows of Wm/We
        #pragma unroll
        for (int i = 0; i < 4; i++) {
            int idx = tid + i * 512;
            int c  = idx & (HH - 1);
            int kk = idx >> 7;
            int kr = (k0 + kk) * HH + c;
            Bs[kk][c] = make_float2(Wm_l[kr], We_l[kr]);
        }
        __syncthreads();
        #pragma unroll
        for (int kk = 0; kk < KC; kk++) {
            float2 b0 = Bs[kk][lane];
            float2 b1 = Bs[kk][lane + 32];
            float2 b2 = Bs[kk][lane + 64];
            float2 b3 = Bs[kk][lane + 96];
            #pragma unroll
            for (int i = 0; i < 8; i++) {
                float2 a = As[kk][warp * 8 + i];   // broadcast LDS.64
                acc[i][0] = ffma2(a, b0, acc[i][0]);
                acc[i][1] = ffma2(a, b1, acc[i][1]);
                acc[i][2] = ffma2(a, b2, acc[i][2]);
                acc[i][3] = ffma2(a, b3, acc[i][3]);
            }
        }
        __syncthreads();
    }

    float bmv[4], bev[4];
    #pragma unroll
    for (int j = 0; j < 4; j++) { bmv[j] = bm_l[lane + 32 * j]; bev[j] = be_l[lane + 32 * j]; }

    #pragma unroll
    for (int i = 0; i < 8; i++) {
        int le = warp * 8 + i;
        float* aggRow = g_agg + rowR[le];
        float* eRow   = g_e + (size_t)(e0 + le) * HH;   // in-place safe: row fully consumed
        #pragma unroll
        for (int j = 0; j < 4; j++) {
            int c = lane + 32 * j;
            atomicAdd(aggRow + c, acc[i][j].x + bmv[j]);  // message + bm scattered to rec
            eRow[c] = acc[i][j].y + bev[j];               // e update + be
        }
    }
}

// ---------------- node kernel: h = [h|agg] @ Wh + bh ----------------
// Tile: 64 nodes x 128 cols, K=256, chunks of 32. blockDim 256 (8 warps, 8 nodes/warp).
#define TN 64
#define NKC 32
__global__ __launch_bounds__(256, 2)
void node_kernel(const float* __restrict__ Wh_l, const float* __restrict__ bh_l) {
    __shared__ float2 As[NKC][TN + 1];  // (a,a); 16.6 KB
    __shared__ float2 Bs[NKC][64];      // (Wh[k][c], Wh[k][c+64]); 16 KB

    const int tid  = threadIdx.x;
    const int warp = tid >> 5;
    const int lane = tid & 31;
    const int n0   = blockIdx.x * TN;

    float2 acc[8][2];
    #pragma unroll
    for (int i = 0; i < 8; i++) { acc[i][0] = make_float2(0.f, 0.f); acc[i][1] = make_float2(0.f, 0.f); }

    for (int k0 = 0; k0 < 2 * HH; k0 += NKC) {
        const int region = k0 >> 7;   // 0: h, 1: agg
        #pragma unroll
        for (int i = 0; i < 8; i++) {
            int idx = tid + i * 256;
            int kk = idx & (NKC - 1);
            int r  = idx >> 5;
            int n  = n0 + r;
            float v = 0.f;
            if (n < NN) {
                if (region == 0) v = g_h  [n * HH + k0 + kk];
                else             v = g_agg[n * HH + (k0 - HH) + kk];
            }
            As[kk][r] = make_float2(v, v);
        }
        #pragma unroll
        for (int i = 0; i < 8; i++) {
            int idx = tid + i * 256;
            int c  = idx & 63;
            int kk = idx >> 6;
            int kr = (k0 + kk) * HH + c;
            Bs[kk][c] = make_float2(Wh_l[kr], Wh_l[kr + 64]);
        }
        __syncthreads();
        #pragma unroll
        for (int kk = 0; kk < NKC; kk++) {
            float2 b0 = Bs[kk][lane];
            float2 b1 = Bs[kk][lane + 32];
            #pragma unroll
            for (int i = 0; i < 8; i++) {
                float2 a = As[kk][warp * 8 + i];
                acc[i][0] = ffma2(a, b0, acc[i][0]);
                acc[i][1] = ffma2(a, b1, acc[i][1]);
            }
        }
        __syncthreads();
    }

    float bh0 = bh_l[lane], bh1 = bh_l[lane + 32], bh2 = bh_l[lane + 64], bh3 = bh_l[lane + 96];
    #pragma unroll
    for (int i = 0; i < 8; i++) {
        int n = n0 + warp * 8 + i;
        if (n < NN) {
            float* hRow = g_h + n * HH;                  // in-place safe
            hRow[lane]      = acc[i][0].x + bh0;
            hRow[lane + 32] = acc[i][1].x + bh1;
            hRow[lane + 64] = acc[i][0].y + bh2;
            hRow[lane + 96] = acc[i][1].y + bh3;
        }
    }
}

// ---------------- global add pool ----------------
__global__ void pool_kernel(const int* __restrict__ batch, float* __restrict__ out) {
    int gidx = blockIdx.x * blockDim.x + threadIdx.x;
    int n = gidx >> 5, lane = gidx & 31;
    if (n >= NN) return;
    int g = batch[n];
    float4 v = reinterpret_cast<const float4*>(g_h + (size_t)n * HH)[lane];
    float* o = out + g * HH + lane * 4;
    atomicAdd(o + 0, v.x); atomicAdd(o + 1, v.y);
    atomicAdd(o + 2, v.z); atomicAdd(o + 3, v.w);
}

// ---------------- launch ----------------
extern "C" void kernel_launch(void* const* d_in, const int* in_sizes, int n_in,
                              void* d_out, int out_size) {
    // Identify inputs by element count (ordered disambiguation for duplicates).
    const float *x = 0, *p = 0, *e_attr = 0, *W_embed = 0, *b_embed = 0, *W_eembed = 0, *b_eembed = 0;
    const float *Wm = 0, *bm = 0, *Wh = 0, *bh = 0, *We = 0, *be = 0;
    const int *edge_index = 0, *batch = 0;
    int n128 = 0, n512 = 0, n196k = 0;
    for (int i = 0; i < n_in; i++) {
        long s = in_sizes[i];
        const void* ptr = d_in[i];
        switch (s) {
            case 3200000:  x         = (const float*)ptr; break;   // [50000,64]
            case 800000:   p         = (const float*)ptr; break;   // [50000,16]
            case 10240000: e_attr    = (const float*)ptr; break;   // [640000,16]
            case 1280000:  edge_index= (const int*)ptr;   break;   // [2,640000]
            case 50000:    batch     = (const int*)ptr;   break;   // [50000]
            case 10240:    W_embed   = (const float*)ptr; break;   // [80,128]
            case 2048:     W_eembed  = (const float*)ptr; break;   // [16,128]
            case 131072:   Wh        = (const float*)ptr; break;   // [4,256,128]
            case 128:  if (n128++ == 0) b_embed = (const float*)ptr; else b_eembed = (const float*)ptr; break;
            case 196608: if (n196k++ == 0) Wm  = (const float*)ptr; else We       = (const float*)ptr; break;
            case 512:
                if (n512 == 0) bm = (const float*)ptr;
                else if (n512 == 1) bh = (const float*)ptr;
                else be = (const float*)ptr;
                n512++;
                break;
            default: break;
        }
    }

    const int* send = edge_index;
    const int* rec  = edge_index + NE;
    float* out = (float*)d_out;

    zero_out_kernel<<<(NG * HH) / 256, 256>>>(out);
    embed_nodes_kernel<<<1024, 128>>>(x, p, W_embed, b_embed);
    embed_edges_kernel<<<2048, 128>>>(e_attr, W_eembed, b_eembed);

    for (int l = 0; l < LL; l++) {
        zero_agg_kernel<<<(NN * HH / 4) / 256, 256>>>();
        edge_kernel<<<NE / TE, 512>>>(send, rec,
                                      Wm + (size_t)l * 3 * HH * HH,
                                      We + (size_t)l * 3 * HH * HH,
                                      bm + l * HH, be + l * HH);
        node_kernel<<<(NN + TN - 1) / TN, 256>>>(Wh + (size_t)l * 2 * HH * HH, bh + l * HH);
    }

    pool_kernel<<<(NN * 32 + 255) / 256, 256>>>(batch, out);
}

// round 5
// speedup vs baseline: 4.0199x; 4.0180x over previous
#include <cuda_runtime.h>
#include <stdint.h>

#define NN 50000
#define NE 640000
#define NG 256
#define HH 128
#define LL 4

// ---------------- scratch (device globals: allocation-free) ----------------
__device__ float g_h[NN * HH];                     // 25.6 MB (tf32-rounded at rest)
__device__ float g_eA[(size_t)NE * HH];            // 327.7 MB (ping)
__device__ float g_eB[(size_t)NE * HH];            // 327.7 MB (pong)
__device__ float g_agg[NN * HH];                   // 25.6 MB
__device__ float g_Wmr[LL * 3 * HH * HH];          // rounded weight copies
__device__ float g_Wer[LL * 3 * HH * HH];
__device__ float g_Whr[LL * 2 * HH * HH];

// ---------------- helpers ----------------
__device__ __forceinline__ uint32_t smem_to_u32(const void* p) {
    uint32_t a;
    asm("{ .reg .u64 t; cvta.to.shared.u64 t, %1; cvt.u32.u64 %0, t; }" : "=r"(a) : "l"(p));
    return a;
}
__device__ __forceinline__ float tf32r(float x) {   // round-to-nearest tf32 (zero-mean error)
    uint32_t u;
    asm("cvt.rna.tf32.f32 %0, %1;" : "=r"(u) : "f"(x));
    return __uint_as_float(u);
}
__device__ __forceinline__ void red2(float* p, float x, float y) {
    asm volatile("red.global.add.v2.f32 [%0], {%1,%2};" :: "l"(p), "f"(x), "f"(y) : "memory");
}
__device__ __forceinline__ void redv4(float* p, float4 v) {
    asm volatile("red.global.add.v4.f32 [%0], {%1,%2,%3,%4};"
                 :: "l"(p), "f"(v.x), "f"(v.y), "f"(v.z), "f"(v.w) : "memory");
}
__device__ __forceinline__ void cpa16(uint32_t dst, const void* src) {
    asm volatile("cp.async.cg.shared.global [%0], [%1], 16;" :: "r"(dst), "l"(src) : "memory");
}
#define CP_COMMIT() asm volatile("cp.async.commit_group;" ::: "memory")
#define CP_WAIT0()  asm volatile("cp.async.wait_group 0;" ::: "memory")

// m16n8k8 tf32 HMMA (sm_80+; valid on plain sm_100 target)
__device__ __forceinline__ void mma8(float* d, const uint32_t* a, uint32_t b0, uint32_t b1) {
    asm volatile("mma.sync.aligned.m16n8k8.row.col.f32.tf32.tf32.f32 "
                 "{%0,%1,%2,%3}, {%4,%5,%6,%7}, {%8,%9}, {%0,%1,%2,%3};"
                 : "+f"(d[0]), "+f"(d[1]), "+f"(d[2]), "+f"(d[3])
                 : "r"(a[0]), "r"(a[1]), "r"(a[2]), "r"(a[3]), "r"(b0), "r"(b1));
}

// ---------------- small utility kernels ----------------
__global__ void zero_out_kernel(float* out) {
    out[blockIdx.x * blockDim.x + threadIdx.x] = 0.0f;
}
__global__ void zero_agg_kernel() {
    int i = blockIdx.x * blockDim.x + threadIdx.x;
    reinterpret_cast<float4*>(g_agg)[i] = make_float4(0.f, 0.f, 0.f, 0.f);
}
__global__ void round_agg_kernel() {
    int i = blockIdx.x * blockDim.x + threadIdx.x;
    float4 v = reinterpret_cast<float4*>(g_agg)[i];
    v.x = tf32r(v.x); v.y = tf32r(v.y); v.z = tf32r(v.z); v.w = tf32r(v.w);
    reinterpret_cast<float4*>(g_agg)[i] = v;
}
__global__ void round_weights_kernel(const float* __restrict__ Wm, const float* __restrict__ We,
                                     const float* __restrict__ Wh) {
    int i = blockIdx.x * blockDim.x + threadIdx.x;   // grid covers 196608
    g_Wmr[i] = tf32r(Wm[i]);
    g_Wer[i] = tf32r(We[i]);
    if (i < LL * 2 * HH * HH) g_Whr[i] = tf32r(Wh[i]);
}

// ---------------- embeddings (FFMA; tiny) — write tf32-rounded results ----------------
__global__ void embed_nodes_kernel(const float* __restrict__ x, const float* __restrict__ p,
                                   const float* __restrict__ W, const float* __restrict__ b) {
    __shared__ float Ws[80 * HH];
    __shared__ float As[16][81];
    int tid = threadIdx.x;
    for (int i = tid; i < 80 * HH; i += 128) Ws[i] = W[i];
    float bias = b[tid];
    __syncthreads();
    for (int chunk = blockIdx.x; chunk < NN / 16; chunk += gridDim.x) {
        int n0 = chunk * 16;
        __syncthreads();
        for (int i = tid; i < 16 * 64; i += 128) { int r = i >> 6, c = i & 63; As[r][c]      = x[(n0 + r) * 64 + c]; }
        for (int i = tid; i < 16 * 16; i += 128) { int r = i >> 4, c = i & 15; As[r][64 + c] = p[(n0 + r) * 16 + c]; }
        __syncthreads();
        #pragma unroll 4
        for (int r = 0; r < 16; r++) {
            float acc = bias;
            #pragma unroll
            for (int k = 0; k < 80; k++) acc += As[r][k] * Ws[k * HH + tid];
            g_h[(n0 + r) * HH + tid] = tf32r(acc);
        }
    }
}
__global__ void embed_edges_kernel(const float* __restrict__ ea,
                                   const float* __restrict__ W, const float* __restrict__ b) {
    __shared__ float Ws[16 * HH];
    __shared__ float As[32][17];
    int tid = threadIdx.x;
    for (int i = tid; i < 16 * HH; i += 128) Ws[i] = W[i];
    float bias = b[tid];
    __syncthreads();
    for (int chunk = blockIdx.x; chunk < NE / 32; chunk += gridDim.x) {
        int e0 = chunk * 32;
        __syncthreads();
        for (int i = tid; i < 32 * 16; i += 128) { int r = i >> 4, c = i & 15; As[r][c] = ea[(e0 + r) * 16 + c]; }
        __syncthreads();
        #pragma unroll 4
        for (int r = 0; r < 32; r++) {
            float acc = bias;
            #pragma unroll
            for (int k = 0; k < 16; k++) acc += As[r][k] * Ws[k * HH + tid];
            g_eA[(size_t)(e0 + r) * HH + tid] = tf32r(acc);
        }
    }
}

// ================= EDGE kernel (mma.sync tf32) =================
// grid (5000, 2): y=0 -> messages (Wm, scatter-add to g_agg); y=1 -> e update (We -> e_out).
// CTA tile: M=128 edges x N=128 cols, K=384 in 12 chunks of 32, cp.async double-buffered.
// 8 warps as 4(M) x 2(N); warp tile 32x64; m16n8k8 frags: 2 Mfrag x 8 Nfrag.
// SMEM: A 2x(128 x stride36 f) = 36864 B; B 2x(32 x stride136 f) = 34816 B; rows @71680.
#define E_SMEM 72704
__global__ __launch_bounds__(256)
void edge_kernel_mma(const int* __restrict__ send, const int* __restrict__ rec,
                     int l, int eflip,
                     const float* __restrict__ bm_l, const float* __restrict__ be_l) {
    extern __shared__ char sm[];
    const uint32_t smb = smem_to_u32(sm);
    const int tid = threadIdx.x, warp = tid >> 5, lane = tid & 31;
    const int g = lane >> 2, t = lane & 3;
    const int warpM = warp >> 1, warpN = warp & 1;
    const int e0 = blockIdx.x * 128;
    const int yy = blockIdx.y;

    const float* W      = yy ? (g_Wer + (size_t)l * 3 * HH * HH) : (g_Wmr + (size_t)l * 3 * HH * HH);
    const float* bias   = yy ? be_l : bm_l;
    const float* e_in   = eflip ? g_eB : g_eA;
    float*       e_out  = eflip ? g_eA : g_eB;

    int* rowSs = (int*)(sm + 71680);
    int* rowRs = (int*)(sm + 72192);
    if (tid < 128) {
        rowSs[tid] = send[e0 + tid] * HH;
        rowRs[tid] = rec [e0 + tid] * HH;
    }
    __syncthreads();

    auto issueA = [&](int c, int s) {
        const int k0 = c * 32, region = k0 >> 7, koff = k0 & 127;
        const uint32_t base = smb + s * 18432;
        #pragma unroll
        for (int i = 0; i < 4; i++) {
            int idx = tid + i * 256;
            int row = idx >> 3, q = idx & 7;
            const float* src;
            if (region == 0)      src = g_h + rowSs[row] + koff + q * 4;
            else if (region == 1) src = g_h + rowRs[row] + koff + q * 4;
            else                  src = e_in + (size_t)(e0 + row) * HH + koff + q * 4;
            cpa16(base + row * 144 + q * 16, src);
        }
    };
    auto issueB = [&](int c, int s) {
        const int k0 = c * 32;
        const uint32_t base = smb + 36864 + s * 17408;
        #pragma unroll
        for (int i = 0; i < 4; i++) {
            int idx = tid + i * 256;
            int k = idx >> 5, m = idx & 31;
            cpa16(base + k * 544 + m * 16, W + (size_t)(k0 + k) * HH + m * 4);
        }
    };

    float acc[2][8][4];
    #pragma unroll
    for (int mf = 0; mf < 2; mf++)
        #pragma unroll
        for (int nf = 0; nf < 8; nf++)
            #pragma unroll
            for (int r = 0; r < 4; r++) acc[mf][nf][r] = 0.f;

    issueA(0, 0); issueB(0, 0); CP_COMMIT();
    for (int c = 0; c < 12; c++) {
        CP_WAIT0();
        __syncthreads();
        if (c + 1 < 12) { issueA(c + 1, (c + 1) & 1); issueB(c + 1, (c + 1) & 1); CP_COMMIT(); }
        const int s = c & 1;
        const uint32_t* A32 = (const uint32_t*)(sm + s * 18432);
        const uint32_t* B32 = (const uint32_t*)(sm + 36864 + s * 17408);
        #pragma unroll
        for (int ks = 0; ks < 4; ks++) {
            uint32_t a[2][4];
            #pragma unroll
            for (int mf = 0; mf < 2; mf++) {
                const int r = warpM * 32 + mf * 16 + g;
                const uint32_t* ap = A32 + r * 36 + ks * 8 + t;
                a[mf][0] = ap[0];
                a[mf][1] = ap[8 * 36];
                a[mf][2] = ap[4];
                a[mf][3] = ap[8 * 36 + 4];
            }
            #pragma unroll
            for (int nf = 0; nf < 8; nf++) {
                const int n = warpN * 64 + nf * 8 + g;
                uint32_t b0 = B32[(ks * 8 + t) * 136 + n];
                uint32_t b1 = B32[(ks * 8 + t + 4) * 136 + n];
                mma8(acc[0][nf], a[0], b0, b1);
                mma8(acc[1][nf], a[1], b0, b1);
            }
        }
    }

    // ---- epilogue ----
    if (yy == 0) {      // messages + bm -> scatter-add into g_agg[rec]
        #pragma unroll
        for (int mf = 0; mf < 2; mf++) {
            const int r0 = warpM * 32 + mf * 16 + g;
            float* d0 = g_agg + rowRs[r0];
            float* dU = g_agg + rowRs[r0 + 8];
            #pragma unroll
            for (int nf = 0; nf < 8; nf++) {
                const int col = warpN * 64 + nf * 8 + 2 * t;
                const float bx = bias[col], by = bias[col + 1];
                red2(d0 + col, acc[mf][nf][0] + bx, acc[mf][nf][1] + by);
                red2(dU + col, acc[mf][nf][2] + bx, acc[mf][nf][3] + by);
            }
        }
    } else {            // e update + be -> e_out (tf32-rounded at rest)
        #pragma unroll
        for (int mf = 0; mf < 2; mf++) {
            const int r0 = warpM * 32 + mf * 16 + g;
            float* p0 = e_out + (size_t)(e0 + r0) * HH;
            float* pU = e_out + (size_t)(e0 + r0 + 8) * HH;
            #pragma unroll
            for (int nf = 0; nf < 8; nf++) {
                const int col = warpN * 64 + nf * 8 + 2 * t;
                const float bx = bias[col], by = bias[col + 1];
                *(float2*)(p0 + col) = make_float2(tf32r(acc[mf][nf][0] + bx), tf32r(acc[mf][nf][1] + by));
                *(float2*)(pU + col) = make_float2(tf32r(acc[mf][nf][2] + bx), tf32r(acc[mf][nf][3] + by));
            }
        }
    }
}

// ================= NODE kernel (mma.sync tf32) =================
// CTA: 128 nodes x 128 cols, K=256 ([h | agg]) in 8 chunks of 32. Same warp layout.
#define N_SMEM 71680
__global__ __launch_bounds__(256)
void node_kernel_mma(int l, const float* __restrict__ bh_l) {
    extern __shared__ char sm[];
    const uint32_t smb = smem_to_u32(sm);
    const int tid = threadIdx.x, warp = tid >> 5, lane = tid & 31;
    const int g = lane >> 2, t = lane & 3;
    const int warpM = warp >> 1, warpN = warp & 1;
    const int n0 = blockIdx.x * 128;
    const float* W = g_Whr + (size_t)l * 2 * HH * HH;

    auto issueA = [&](int c, int s) {
        const float* srcb = (c < 4) ? g_h : g_agg;
        const int koff = (c * 32) & 127;
        const uint32_t base = smb + s * 18432;
        #pragma unroll
        for (int i = 0; i < 4; i++) {
            int idx = tid + i * 256;
            int row = idx >> 3, q = idx & 7;
            int n = n0 + row; if (n >= NN) n = NN - 1;      // clamp; writes guarded later
            cpa16(base + row * 144 + q * 16, srcb + (size_t)n * HH + koff + q * 4);
        }
    };
    auto issueB = [&](int c, int s) {
        const int k0 = c * 32;
        const uint32_t base = smb + 36864 + s * 17408;
        #pragma unroll
        for (int i = 0; i < 4; i++) {
            int idx = tid + i * 256;
            int k = idx >> 5, m = idx & 31;
            cpa16(base + k * 544 + m * 16, W + (size_t)(k0 + k) * HH + m * 4);
        }
    };

    float acc[2][8][4];
    #pragma unroll
    for (int mf = 0; mf < 2; mf++)
        #pragma unroll
        for (int nf = 0; nf < 8; nf++)
            #pragma unroll
            for (int r = 0; r < 4; r++) acc[mf][nf][r] = 0.f;

    issueA(0, 0); issueB(0, 0); CP_COMMIT();
    for (int c = 0; c < 8; c++) {
        CP_WAIT0();
        __syncthreads();
        if (c + 1 < 8) { issueA(c + 1, (c + 1) & 1); issueB(c + 1, (c + 1) & 1); CP_COMMIT(); }
        const int s = c & 1;
        const uint32_t* A32 = (const uint32_t*)(sm + s * 18432);
        const uint32_t* B32 = (const uint32_t*)(sm + 36864 + s * 17408);
        #pragma unroll
        for (int ks = 0; ks < 4; ks++) {
            uint32_t a[2][4];
            #pragma unroll
            for (int mf = 0; mf < 2; mf++) {
                const int r = warpM * 32 + mf * 16 + g;
                const uint32_t* ap = A32 + r * 36 + ks * 8 + t;
                a[mf][0] = ap[0];
                a[mf][1] = ap[8 * 36];
                a[mf][2] = ap[4];
                a[mf][3] = ap[8 * 36 + 4];
            }
            #pragma unroll
            for (int nf = 0; nf < 8; nf++) {
                const int n = warpN * 64 + nf * 8 + g;
                uint32_t b0 = B32[(ks * 8 + t) * 136 + n];
                uint32_t b1 = B32[(ks * 8 + t + 4) * 136 + n];
                mma8(acc[0][nf], a[0], b0, b1);
                mma8(acc[1][nf], a[1], b0, b1);
            }
        }
    }

    // epilogue: in-place h update (CTA owns its rows; reads all done)
    #pragma unroll
    for (int mf = 0; mf < 2; mf++) {
        const int r0 = warpM * 32 + mf * 16 + g;
        const int nA = n0 + r0, nB = n0 + r0 + 8;
        #pragma unroll
        for (int nf = 0; nf < 8; nf++) {
            const int col = warpN * 64 + nf * 8 + 2 * t;
            const float bx = bh_l[col], by = bh_l[col + 1];
            if (nA < NN)
                *(float2*)(g_h + (size_t)nA * HH + col) =
                    make_float2(tf32r(acc[mf][nf][0] + bx), tf32r(acc[mf][nf][1] + by));
            if (nB < NN)
                *(float2*)(g_h + (size_t)nB * HH + col) =
                    make_float2(tf32r(acc[mf][nf][2] + bx), tf32r(acc[mf][nf][3] + by));
        }
    }
}

// ---------------- global add pool ----------------
__global__ void pool_kernel(const int* __restrict__ batch, float* __restrict__ out) {
    int gidx = blockIdx.x * blockDim.x + threadIdx.x;
    int n = gidx >> 5, lane = gidx & 31;
    if (n >= NN) return;
    int gr = batch[n];
    float4 v = reinterpret_cast<const float4*>(g_h + (size_t)n * HH)[lane];
    redv4(out + gr * HH + lane * 4, v);
}

// ---------------- launch ----------------
extern "C" void kernel_launch(void* const* d_in, const int* in_sizes, int n_in,
                              void* d_out, int out_size) {
    const float *x = 0, *p = 0, *e_attr = 0, *W_embed = 0, *b_embed = 0, *W_eembed = 0, *b_eembed = 0;
    const float *Wm = 0, *bm = 0, *Wh = 0, *bh = 0, *We = 0, *be = 0;
    const int *edge_index = 0, *batch = 0;
    int n128 = 0, n512 = 0, n196k = 0;
    for (int i = 0; i < n_in; i++) {
        long s = in_sizes[i];
        const void* ptr = d_in[i];
        switch (s) {
            case 3200000:  x          = (const float*)ptr; break;
            case 800000:   p          = (const float*)ptr; break;
            case 10240000: e_attr     = (const float*)ptr; break;
            case 1280000:  edge_index = (const int*)ptr;   break;
            case 50000:    batch      = (const int*)ptr;   break;
            case 10240:    W_embed    = (const float*)ptr; break;
            case 2048:     W_eembed   = (const float*)ptr; break;
            case 131072:   Wh         = (const float*)ptr; break;
            case 128:  if (n128++ == 0) b_embed = (const float*)ptr; else b_eembed = (const float*)ptr; break;
            case 196608: if (n196k++ == 0) Wm = (const float*)ptr; else We = (const float*)ptr; break;
            case 512:
                if (n512 == 0) bm = (const float*)ptr;
                else if (n512 == 1) bh = (const float*)ptr;
                else be = (const float*)ptr;
                n512++;
                break;
            default: break;
        }
    }

    cudaFuncSetAttribute(edge_kernel_mma, cudaFuncAttributeMaxDynamicSharedMemorySize, E_SMEM);
    cudaFuncSetAttribute(node_kernel_mma, cudaFuncAttributeMaxDynamicSharedMemorySize, N_SMEM);

    const int* send = edge_index;
    const int* rec  = edge_index + NE;
    float* out = (float*)d_out;

    round_weights_kernel<<<(LL * 3 * HH * HH) / 256, 256>>>(Wm, We, Wh);
    zero_out_kernel<<<(NG * HH) / 256, 256>>>(out);
    embed_nodes_kernel<<<1024, 128>>>(x, p, W_embed, b_embed);
    embed_edges_kernel<<<2048, 128>>>(e_attr, W_eembed, b_eembed);

    for (int l = 0; l < LL; l++) {
        zero_agg_kernel<<<(NN * HH / 4) / 256, 256>>>();
        edge_kernel_mma<<<dim3(NE / 128, 2), 256, E_SMEM>>>(send, rec, l, l & 1,
                                                            bm + l * HH, be + l * HH);
        round_agg_kernel<<<(NN * HH / 4) / 256, 256>>>();
        node_kernel_mma<<<(NN + 127) / 128, 256, N_SMEM>>>(l, bh + l * HH);
    }

    pool_kernel<<<(NN * 32 + 255) / 256, 256>>>(batch, out);
}